// round 4
// baseline (speedup 1.0000x reference)
#include <cuda_runtime.h>
#include <math.h>

#define U_N 100000
#define I_N 50000
#define E_N 2000000
#define D_N 128
#define B_N 4096

#define CHUNK 1024
#define NCH_U ((U_N + CHUNK - 1) / CHUNK)   // 98
#define NCH_I ((I_N + CHUNK - 1) / CHUNK)   // 49

// ---------------- device scratch (static, allocation-free) ----------------
__device__ char  g_h8_u[2][(size_t)U_N * D_N];  // 2 x 12.8 MB int8 rows
__device__ char  g_h8_i[2][(size_t)I_N * D_N];  // 2 x  6.4 MB
__device__ float g_su[2][U_N];                  // per-row dequant scales
__device__ float g_si[2][I_N];
__device__ int   g_deg_u[U_N];
__device__ int   g_deg_i[I_N];
__device__ int   g_row_u[U_N + 1];
__device__ int   g_row_i[I_N + 1];
__device__ int   g_cur_u[U_N];
__device__ int   g_cur_i[I_N];
__device__ int   g_chunk_u[NCH_U];
__device__ int   g_chunk_i[NCH_I];
__device__ int2  g_adj_u[E_N];                  // {item, norm-bits} CSR by user
__device__ int2  g_adj_i[E_N];                  // {user, norm-bits} CSR by item
__device__ float g_acc_u[(size_t)B_N * D_N];
__device__ float g_acc_i[(size_t)B_N * D_N];

// ---------------- CSR construction ----------------

__global__ void zero_deg_kernel() {
    int t = blockIdx.x * blockDim.x + threadIdx.x;
    if (t < U_N) g_deg_u[t] = 0;
    if (t < I_N) g_deg_i[t] = 0;
}

__global__ void degree_kernel(const int* __restrict__ u_idx,
                              const int* __restrict__ i_idx) {
    int e = blockIdx.x * blockDim.x + threadIdx.x;
    if (e >= E_N) return;
    atomicAdd(&g_deg_u[u_idx[e]], 1);
    atomicAdd(&g_deg_i[i_idx[e]], 1);
}

// Phase A: per-chunk (1024 elems) partial sums. Blocks [0,NCH_U) -> U, rest -> I.
__global__ void scan_partial_kernel() {
    bool isU = blockIdx.x < NCH_U;
    const int* deg = isU ? g_deg_u : g_deg_i;
    int* part      = isU ? g_chunk_u : g_chunk_i;
    int  c         = isU ? blockIdx.x : blockIdx.x - NCH_U;
    int  n         = isU ? U_N : I_N;

    int base = c * CHUNK + threadIdx.x * 4;
    int s = 0;
    #pragma unroll
    for (int j = 0; j < 4; j++) {
        int idx = base + j;
        if (idx < n) s += deg[idx];
    }
    #pragma unroll
    for (int o = 16; o > 0; o >>= 1) s += __shfl_down_sync(0xFFFFFFFFu, s, o);
    __shared__ int ws[8];
    if ((threadIdx.x & 31) == 0) ws[threadIdx.x >> 5] = s;
    __syncthreads();
    if (threadIdx.x < 8) {
        int v = ws[threadIdx.x];
        #pragma unroll
        for (int o = 4; o > 0; o >>= 1) v += __shfl_down_sync(0xFFu, v, o);
        if (threadIdx.x == 0) part[c] = v;
    }
}

// Phase B: one block scans both partial arrays (exclusive).
__global__ void scan_chunkoff_kernel() {
    __shared__ int buf[128];
    int t = threadIdx.x;

    int v = (t < NCH_U) ? g_chunk_u[t] : 0;
    buf[t] = v; __syncthreads();
    #pragma unroll
    for (int o = 1; o < 128; o <<= 1) {
        int x = (t >= o) ? buf[t - o] : 0;
        __syncthreads(); buf[t] += x; __syncthreads();
    }
    if (t < NCH_U) g_chunk_u[t] = buf[t] - v;
    __syncthreads();

    int v2 = (t < NCH_I) ? g_chunk_i[t] : 0;
    buf[t] = v2; __syncthreads();
    #pragma unroll
    for (int o = 1; o < 128; o <<= 1) {
        int x = (t >= o) ? buf[t - o] : 0;
        __syncthreads(); buf[t] += x; __syncthreads();
    }
    if (t < NCH_I) g_chunk_i[t] = buf[t] - v2;
    if (t == 0) { g_row_u[U_N] = E_N; g_row_i[I_N] = E_N; }
}

// Phase C: per-chunk local exclusive scan + chunk base; also init cursors.
__global__ void scan_final_kernel() {
    bool isU = blockIdx.x < NCH_U;
    const int* deg = isU ? g_deg_u : g_deg_i;
    int* row       = isU ? g_row_u : g_row_i;
    int* cur       = isU ? g_cur_u : g_cur_i;
    int  c         = isU ? blockIdx.x : blockIdx.x - NCH_U;
    int  n         = isU ? U_N : I_N;
    int  cbase     = isU ? g_chunk_u[c] : g_chunk_i[c];

    int base = c * CHUNK + threadIdx.x * 4;
    int d[4], e[4];
    int s = 0;
    #pragma unroll
    for (int j = 0; j < 4; j++) {
        int idx = base + j;
        d[j] = (idx < n) ? deg[idx] : 0;
        e[j] = s;
        s += d[j];
    }
    int lane = threadIdx.x & 31, w = threadIdx.x >> 5;
    int inc = s;
    #pragma unroll
    for (int o = 1; o < 32; o <<= 1) {
        int x = __shfl_up_sync(0xFFFFFFFFu, inc, o);
        if (lane >= o) inc += x;
    }
    __shared__ int ws[8];
    if (lane == 31) ws[w] = inc;
    __syncthreads();
    if (threadIdx.x < 8) {
        int v = ws[threadIdx.x];
        #pragma unroll
        for (int o = 1; o < 8; o <<= 1) {
            int x = __shfl_up_sync(0xFFu, v, o);
            if ((int)threadIdx.x >= o) v += x;
        }
        ws[threadIdx.x] = v;
    }
    __syncthreads();
    int excl = inc - s + (w > 0 ? ws[w - 1] : 0) + cbase;
    #pragma unroll
    for (int j = 0; j < 4; j++) {
        int idx = base + j;
        if (idx < n) { int r = excl + e[j]; row[idx] = r; cur[idx] = r; }
    }
}

// Fill both CSR adjacency arrays, norm packed with the column index.
__global__ void fill_kernel(const int* __restrict__ u_idx,
                            const int* __restrict__ i_idx) {
    int e = blockIdx.x * blockDim.x + threadIdx.x;
    if (e >= E_N) return;
    int u = u_idx[e];
    int i = i_idx[e];
    float nf = rsqrtf((float)g_deg_u[u] * (float)g_deg_i[i]);
    int nb = __float_as_int(nf);
    int pu = atomicAdd(&g_cur_u[u], 1);
    g_adj_u[pu] = make_int2(i, nb);
    int pi = atomicAdd(&g_cur_i[i], 1);
    g_adj_i[pi] = make_int2(u, nb);
}

// ---------------- quantization helpers ----------------
__device__ __forceinline__ char4 quant4(float a0, float a1, float a2, float a3,
                                        float inv) {
    char4 q;
    q.x = (char)__float2int_rn(a0 * inv);
    q.y = (char)__float2int_rn(a1 * inv);
    q.z = (char)__float2int_rn(a2 * inv);
    q.w = (char)__float2int_rn(a3 * inv);
    return q;
}

// warp max-reduce of the 4 local accumulator magnitudes -> row scale
__device__ __forceinline__ float warp_row_max(float a0, float a1, float a2, float a3) {
    float m = fmaxf(fmaxf(fabsf(a0), fabsf(a1)), fmaxf(fabsf(a2), fabsf(a3)));
    #pragma unroll
    for (int o = 16; o > 0; o >>= 1)
        m = fmaxf(m, __shfl_xor_sync(0xFFFFFFFFu, m, o));
    return m;
}

// ---------------- fp32 -> int8 input conversion (warp per row) ----------------
__global__ void convert_kernel(const float4* __restrict__ user_feat,
                               const float4* __restrict__ item_feat) {
    int w = (blockIdx.x * blockDim.x + threadIdx.x) >> 5;
    int lane = threadIdx.x & 31;
    const float4* src; char4* dst; float* sc; int d;
    if (w < U_N)            { d = w;        src = user_feat; dst = (char4*)g_h8_u[0]; sc = g_su[0]; }
    else if (w < U_N + I_N) { d = w - U_N;  src = item_feat; dst = (char4*)g_h8_i[0]; sc = g_si[0]; }
    else return;

    float4 v = src[(size_t)d * 32 + lane];
    float m = warp_row_max(v.x, v.y, v.z, v.w);
    m = fmaxf(m, 1e-20f);
    float inv = 127.0f / m;
    dst[(size_t)d * 32 + lane] = quant4(v.x, v.y, v.z, v.w, inv);
    if (lane == 0) sc[d] = m * (1.0f / 127.0f);
}

// ---------------- propagation: gather over int8 rows, fp32 accum ----------------
// One warp per destination row; lane owns 4 dims (one char4).
__global__ void gather_kernel(const char4* __restrict__ s8_u,
                              const char4* __restrict__ s8_i,
                              const float* __restrict__ sc_u,
                              const float* __restrict__ sc_i,
                              char4* __restrict__ d8_u,
                              char4* __restrict__ d8_i,
                              float* __restrict__ dsc_u,
                              float* __restrict__ dsc_i) {
    int w = (blockIdx.x * blockDim.x + threadIdx.x) >> 5;
    int lane = threadIdx.x & 31;

    const int* rp; const int2* adj;
    const char4* src; const float* ssc;
    const char4* self; const float* selfsc;
    char4* dst; float* dsc; int d;
    if (w < U_N) {
        d = w; rp = g_row_u; adj = g_adj_u;
        src = s8_i; ssc = sc_i; self = s8_u; selfsc = sc_u;
        dst = d8_u; dsc = dsc_u;
    } else if (w < U_N + I_N) {
        d = w - U_N; rp = g_row_i; adj = g_adj_i;
        src = s8_u; ssc = sc_u; self = s8_i; selfsc = sc_i;
        dst = d8_i; dsc = dsc_i;
    } else return;

    int start = rp[d];
    int end   = rp[d + 1];

    char4 sq = self[(size_t)d * 32 + lane];
    float ss = selfsc[d];
    float a0 = ss * (float)sq.x, a1 = ss * (float)sq.y;
    float a2 = ss * (float)sq.z, a3 = ss * (float)sq.w;

    int k = start;
    for (; k + 4 <= end; k += 4) {
        int2 e0 = adj[k], e1 = adj[k + 1], e2 = adj[k + 2], e3 = adj[k + 3];
        char4 v0 = src[(size_t)e0.x * 32 + lane];
        char4 v1 = src[(size_t)e1.x * 32 + lane];
        char4 v2 = src[(size_t)e2.x * 32 + lane];
        char4 v3 = src[(size_t)e3.x * 32 + lane];
        float c0 = __int_as_float(e0.y) * ssc[e0.x];
        float c1 = __int_as_float(e1.y) * ssc[e1.x];
        float c2 = __int_as_float(e2.y) * ssc[e2.x];
        float c3 = __int_as_float(e3.y) * ssc[e3.x];
        a0 += c0 * (float)v0.x; a1 += c0 * (float)v0.y; a2 += c0 * (float)v0.z; a3 += c0 * (float)v0.w;
        a0 += c1 * (float)v1.x; a1 += c1 * (float)v1.y; a2 += c1 * (float)v1.z; a3 += c1 * (float)v1.w;
        a0 += c2 * (float)v2.x; a1 += c2 * (float)v2.y; a2 += c2 * (float)v2.z; a3 += c2 * (float)v2.w;
        a0 += c3 * (float)v3.x; a1 += c3 * (float)v3.y; a2 += c3 * (float)v3.z; a3 += c3 * (float)v3.w;
    }
    for (; k < end; k++) {
        int2 e0 = adj[k];
        char4 v0 = src[(size_t)e0.x * 32 + lane];
        float c0 = __int_as_float(e0.y) * ssc[e0.x];
        a0 += c0 * (float)v0.x; a1 += c0 * (float)v0.y; a2 += c0 * (float)v0.z; a3 += c0 * (float)v0.w;
    }

    float m = warp_row_max(a0, a1, a2, a3);
    m = fmaxf(m, 1e-20f);
    float inv = 127.0f / m;
    dst[(size_t)d * 32 + lane] = quant4(a0, a1, a2, a3, inv);
    if (lane == 0) dsc[d] = m * (1.0f / 127.0f);
}

// ---------------- scoring path ----------------

__global__ void acc_init_kernel(const float4* __restrict__ user_feat,
                                const float4* __restrict__ item_feat,
                                const int* __restrict__ ui,
                                const int* __restrict__ ii,
                                float* __restrict__ loss_out,
                                int has_loss) {
    int t = blockIdx.x * blockDim.x + threadIdx.x;  // over B*32
    const int per_row = D_N / 4;
    if (t >= B_N * per_row) return;
    int b = t / per_row;
    int d = t - b * per_row;
    ((float4*)g_acc_u)[t] = user_feat[(size_t)ui[b] * per_row + d];
    ((float4*)g_acc_i)[t] = item_feat[(size_t)ii[b] * per_row + d];
    if (t == 0 && has_loss) *loss_out = 0.0f;
}

// acc += coef * dequant(int8 rows just produced)
__global__ void acc_gather_kernel(const char4* __restrict__ h8_u,
                                  const char4* __restrict__ h8_i,
                                  const float* __restrict__ sc_u,
                                  const float* __restrict__ sc_i,
                                  const int* __restrict__ ui,
                                  const int* __restrict__ ii,
                                  float coef) {
    int t = blockIdx.x * blockDim.x + threadIdx.x;
    const int per_row = D_N / 4;
    if (t >= B_N * per_row) return;
    int b = t / per_row;
    int d = t - b * per_row;

    int ru = ui[b];
    char4 q = h8_u[(size_t)ru * per_row + d];
    float cu = coef * sc_u[ru];
    float4 a = ((float4*)g_acc_u)[t];
    a.x += cu * (float)q.x; a.y += cu * (float)q.y;
    a.z += cu * (float)q.z; a.w += cu * (float)q.w;
    ((float4*)g_acc_u)[t] = a;

    int ri = ii[b];
    char4 q2 = h8_i[(size_t)ri * per_row + d];
    float ci = coef * sc_i[ri];
    float4 ai = ((float4*)g_acc_i)[t];
    ai.x += ci * (float)q2.x; ai.y += ci * (float)q2.y;
    ai.z += ci * (float)q2.z; ai.w += ci * (float)q2.w;
    ((float4*)g_acc_i)[t] = ai;
}

__global__ void score_kernel(const float* __restrict__ labels,
                             float* __restrict__ pred_out,
                             float* __restrict__ loss_out,
                             int has_loss) {
    int warp = (blockIdx.x * blockDim.x + threadIdx.x) >> 5;
    int lane = threadIdx.x & 31;
    if (warp >= B_N) return;

    const float4* au = (const float4*)(g_acc_u + (size_t)warp * D_N);
    const float4* ai = (const float4*)(g_acc_i + (size_t)warp * D_N);
    float4 a = au[lane];
    float4 b = ai[lane];
    float s = a.x * b.x + a.y * b.y + a.z * b.z + a.w * b.w;
    #pragma unroll
    for (int off = 16; off > 0; off >>= 1)
        s += __shfl_down_sync(0xFFFFFFFFu, s, off);

    if (lane == 0) {
        float z = 1.0f / (1.0f + expf(-s));
        pred_out[warp] = z;
        if (has_loss) {
            float lbl = labels[warp];
            float term = fmaxf(z, 0.0f) - z * lbl + log1pf(expf(-fabsf(z)));
            atomicAdd(loss_out, term * (1.0f / (float)B_N));
        }
    }
}

// ---------------- host launch ----------------
extern "C" void kernel_launch(void* const* d_in, const int* in_sizes, int n_in,
                              void* d_out, int out_size) {
    const float* user_feat = (const float*)d_in[0];
    const float* item_feat = (const float*)d_in[1];
    const int*   u_idx     = (const int*)d_in[2];
    const int*   i_idx     = (const int*)d_in[3];
    const int*   ui        = (const int*)d_in[4];
    const int*   ii        = (const int*)d_in[5];
    const float* labels    = (const float*)d_in[6];

    float* out = (float*)d_out;
    int has_loss = (out_size > B_N) ? 1 : 0;
    float* pred_out = out + (out_size - B_N);
    float* loss_out = out;

    char* hu_base; char* hi_base; float* su_base; float* si_base;
    cudaGetSymbolAddress((void**)&hu_base, g_h8_u);
    cudaGetSymbolAddress((void**)&hi_base, g_h8_i);
    cudaGetSymbolAddress((void**)&su_base, g_su);
    cudaGetSymbolAddress((void**)&si_base, g_si);
    char*  hu[2] = { hu_base, hu_base + (size_t)U_N * D_N };
    char*  hi[2] = { hi_base, hi_base + (size_t)I_N * D_N };
    float* su[2] = { su_base, su_base + U_N };
    float* si[2] = { si_base, si_base + I_N };

    const int T = 256;
    const int acc_blocks = (B_N * (D_N / 4) + T - 1) / T;
    const int row_warp_blocks = ((U_N + I_N) * 32 + T - 1) / T;

    // 1) CSR build
    zero_deg_kernel<<<(U_N + T - 1) / T, T>>>();
    degree_kernel<<<(E_N + T - 1) / T, T>>>(u_idx, i_idx);
    scan_partial_kernel<<<NCH_U + NCH_I, 256>>>();
    scan_chunkoff_kernel<<<1, 128>>>();
    scan_final_kernel<<<NCH_U + NCH_I, 256>>>();
    fill_kernel<<<(E_N + T - 1) / T, T>>>(u_idx, i_idx);

    // 2) int8 source buffers + scoring accumulators (layer-0 term, exact fp32)
    convert_kernel<<<row_warp_blocks, T>>>((const float4*)user_feat,
                                           (const float4*)item_feat);
    acc_init_kernel<<<acc_blocks, T>>>((const float4*)user_feat,
                                       (const float4*)item_feat,
                                       ui, ii, loss_out, has_loss);

    // 3) three propagation layers (ping-pong int8 buffers)
    const float coefs[3] = { 1.0f / 2.0f, 1.0f / 3.0f, 1.0f / 4.0f };
    int cur = 0;
    for (int l = 0; l < 3; l++) {
        int nxt = 1 - cur;
        gather_kernel<<<row_warp_blocks, T>>>((const char4*)hu[cur],
                                              (const char4*)hi[cur],
                                              su[cur], si[cur],
                                              (char4*)hu[nxt], (char4*)hi[nxt],
                                              su[nxt], si[nxt]);
        acc_gather_kernel<<<acc_blocks, T>>>((const char4*)hu[nxt],
                                             (const char4*)hi[nxt],
                                             su[nxt], si[nxt],
                                             ui, ii, coefs[l]);
        cur = nxt;
    }

    // 4) scoring + loss
    score_kernel<<<(B_N * 32 + T - 1) / T, T>>>(labels, pred_out, loss_out, has_loss);
}

// round 5
// speedup vs baseline: 1.5076x; 1.5076x over previous
#include <cuda_runtime.h>
#include <cuda_fp16.h>
#include <math.h>

#define U_N 100000
#define I_N 50000
#define E_N 2000000
#define D_N 128
#define B_N 4096

#define FP8_SCALE 256.0f
#define FP8_INV   (1.0f / 256.0f)

#define CHUNK 1024
#define NCH_U ((U_N + CHUNK - 1) / CHUNK)   // 98
#define NCH_I ((I_N + CHUNK - 1) / CHUNK)   // 49

// ---------------- device scratch (static, allocation-free) ----------------
// fp8 rows: D_N bytes per row = 32 uint32 per row.
__device__ unsigned g_f8_u[2][(size_t)U_N * (D_N / 4)];  // 2 x 12.8 MB
__device__ unsigned g_f8_i[2][(size_t)I_N * (D_N / 4)];  // 2 x  6.4 MB
__device__ int   g_deg_u[U_N];
__device__ int   g_deg_i[I_N];
__device__ int   g_row_u[U_N + 1];
__device__ int   g_row_i[I_N + 1];
__device__ int   g_cur_u[U_N];
__device__ int   g_cur_i[I_N];
__device__ int   g_chunk_u[NCH_U];
__device__ int   g_chunk_i[NCH_I];
__device__ int2  g_adj_u[E_N];   // {item, norm as duplicated half2}
__device__ int2  g_adj_i[E_N];   // {user, norm as duplicated half2}
__device__ float g_acc_u[(size_t)B_N * D_N];
__device__ float g_acc_i[(size_t)B_N * D_N];

// ---------------- fp8 conversion helpers (fast packed class) ----------------
__device__ __forceinline__ __half2 e4m3x2_to_h2(unsigned short s) {
    unsigned r;
    asm("cvt.rn.f16x2.e4m3x2 %0, %1;" : "=r"(r) : "h"(s));
    return *reinterpret_cast<__half2*>(&r);
}
__device__ __forceinline__ unsigned short h2_to_e4m3x2(__half2 h) {
    unsigned short s;
    unsigned hr = *reinterpret_cast<unsigned*>(&h);
    asm("cvt.rn.satfinite.e4m3x2.f16x2 %0, %1;" : "=h"(s) : "r"(hr));
    return s;
}
__device__ __forceinline__ unsigned pack_f8x4(__half2 lo, __half2 hi) {
    return (unsigned)h2_to_e4m3x2(lo) | ((unsigned)h2_to_e4m3x2(hi) << 16);
}

// ---------------- CSR construction ----------------

__global__ void zero_deg_kernel() {
    int t = blockIdx.x * blockDim.x + threadIdx.x;
    if (t < U_N) g_deg_u[t] = 0;
    if (t < I_N) g_deg_i[t] = 0;
}

__global__ void degree_kernel(const int* __restrict__ u_idx,
                              const int* __restrict__ i_idx) {
    int e = blockIdx.x * blockDim.x + threadIdx.x;
    if (e >= E_N) return;
    atomicAdd(&g_deg_u[u_idx[e]], 1);
    atomicAdd(&g_deg_i[i_idx[e]], 1);
}

// Phase A: per-chunk (1024 elems) partial sums.
__global__ void scan_partial_kernel() {
    bool isU = blockIdx.x < NCH_U;
    const int* deg = isU ? g_deg_u : g_deg_i;
    int* part      = isU ? g_chunk_u : g_chunk_i;
    int  c         = isU ? blockIdx.x : blockIdx.x - NCH_U;
    int  n         = isU ? U_N : I_N;

    int base = c * CHUNK + threadIdx.x * 4;
    int s = 0;
    #pragma unroll
    for (int j = 0; j < 4; j++) {
        int idx = base + j;
        if (idx < n) s += deg[idx];
    }
    #pragma unroll
    for (int o = 16; o > 0; o >>= 1) s += __shfl_down_sync(0xFFFFFFFFu, s, o);
    __shared__ int ws[8];
    if ((threadIdx.x & 31) == 0) ws[threadIdx.x >> 5] = s;
    __syncthreads();
    if (threadIdx.x < 8) {
        int v = ws[threadIdx.x];
        #pragma unroll
        for (int o = 4; o > 0; o >>= 1) v += __shfl_down_sync(0xFFu, v, o);
        if (threadIdx.x == 0) part[c] = v;
    }
}

// Phase B: one block scans both partial arrays (exclusive).
__global__ void scan_chunkoff_kernel() {
    __shared__ int buf[128];
    int t = threadIdx.x;

    int v = (t < NCH_U) ? g_chunk_u[t] : 0;
    buf[t] = v; __syncthreads();
    #pragma unroll
    for (int o = 1; o < 128; o <<= 1) {
        int x = (t >= o) ? buf[t - o] : 0;
        __syncthreads(); buf[t] += x; __syncthreads();
    }
    if (t < NCH_U) g_chunk_u[t] = buf[t] - v;
    __syncthreads();

    int v2 = (t < NCH_I) ? g_chunk_i[t] : 0;
    buf[t] = v2; __syncthreads();
    #pragma unroll
    for (int o = 1; o < 128; o <<= 1) {
        int x = (t >= o) ? buf[t - o] : 0;
        __syncthreads(); buf[t] += x; __syncthreads();
    }
    if (t < NCH_I) g_chunk_i[t] = buf[t] - v2;
    if (t == 0) { g_row_u[U_N] = E_N; g_row_i[I_N] = E_N; }
}

// Phase C: per-chunk local exclusive scan + chunk base; also init cursors.
__global__ void scan_final_kernel() {
    bool isU = blockIdx.x < NCH_U;
    const int* deg = isU ? g_deg_u : g_deg_i;
    int* row       = isU ? g_row_u : g_row_i;
    int* cur       = isU ? g_cur_u : g_cur_i;
    int  c         = isU ? blockIdx.x : blockIdx.x - NCH_U;
    int  n         = isU ? U_N : I_N;
    int  cbase     = isU ? g_chunk_u[c] : g_chunk_i[c];

    int base = c * CHUNK + threadIdx.x * 4;
    int d[4], e[4];
    int s = 0;
    #pragma unroll
    for (int j = 0; j < 4; j++) {
        int idx = base + j;
        d[j] = (idx < n) ? deg[idx] : 0;
        e[j] = s;
        s += d[j];
    }
    int lane = threadIdx.x & 31, w = threadIdx.x >> 5;
    int inc = s;
    #pragma unroll
    for (int o = 1; o < 32; o <<= 1) {
        int x = __shfl_up_sync(0xFFFFFFFFu, inc, o);
        if (lane >= o) inc += x;
    }
    __shared__ int ws[8];
    if (lane == 31) ws[w] = inc;
    __syncthreads();
    if (threadIdx.x < 8) {
        int v = ws[threadIdx.x];
        #pragma unroll
        for (int o = 1; o < 8; o <<= 1) {
            int x = __shfl_up_sync(0xFFu, v, o);
            if ((int)threadIdx.x >= o) v += x;
        }
        ws[threadIdx.x] = v;
    }
    __syncthreads();
    int excl = inc - s + (w > 0 ? ws[w - 1] : 0) + cbase;
    #pragma unroll
    for (int j = 0; j < 4; j++) {
        int idx = base + j;
        if (idx < n) { int r = excl + e[j]; row[idx] = r; cur[idx] = r; }
    }
}

// Fill both CSR adjacency arrays; norm stored as duplicated half2.
__global__ void fill_kernel(const int* __restrict__ u_idx,
                            const int* __restrict__ i_idx) {
    int e = blockIdx.x * blockDim.x + threadIdx.x;
    if (e >= E_N) return;
    int u = u_idx[e];
    int i = i_idx[e];
    float nf = rsqrtf((float)g_deg_u[u] * (float)g_deg_i[i]);
    __half2 h2 = __half2half2(__float2half_rn(nf));
    int nb = *reinterpret_cast<int*>(&h2);
    int pu = atomicAdd(&g_cur_u[u], 1);
    g_adj_u[pu] = make_int2(i, nb);
    int pi = atomicAdd(&g_cur_i[i], 1);
    g_adj_i[pi] = make_int2(u, nb);
}

// ---------------- fp32 -> fp8 input conversion ----------------
// One thread per uint32 (4 dims): reads float4, scales by S, packs e4m3x4.
__global__ void convert_kernel(const float4* __restrict__ user_feat,
                               const float4* __restrict__ item_feat) {
    int t = blockIdx.x * blockDim.x + threadIdx.x;
    const int nu = U_N * (D_N / 4);
    const int ni = I_N * (D_N / 4);
    float4 v; unsigned* dst; int o;
    if (t < nu)            { v = user_feat[t]; dst = g_f8_u[0]; o = t; }
    else if (t < nu + ni)  { v = item_feat[t - nu]; dst = g_f8_i[0]; o = t - nu; }
    else return;
    __half2 lo = __floats2half2_rn(v.x * FP8_SCALE, v.y * FP8_SCALE);
    __half2 hi = __floats2half2_rn(v.z * FP8_SCALE, v.w * FP8_SCALE);
    dst[o] = pack_f8x4(lo, hi);
}

// ---------------- propagation: gather over fp8 rows, half2 accum ----------------
// One warp per destination row; lane owns 4 dims (one uint32 of fp8).
__global__ void gather_kernel(const unsigned* __restrict__ s8_u,
                              const unsigned* __restrict__ s8_i,
                              unsigned* __restrict__ d8_u,
                              unsigned* __restrict__ d8_i) {
    int w = (blockIdx.x * blockDim.x + threadIdx.x) >> 5;
    int lane = threadIdx.x & 31;

    const int* rp; const int2* adj;
    const unsigned* src; const unsigned* self; unsigned* dst; int d;
    if (w < U_N) {
        d = w; rp = g_row_u; adj = g_adj_u;
        src = s8_i; self = s8_u; dst = d8_u;
    } else if (w < U_N + I_N) {
        d = w - U_N; rp = g_row_i; adj = g_adj_i;
        src = s8_u; self = s8_i; dst = d8_i;
    } else return;

    int start = rp[d];
    int end   = rp[d + 1];

    unsigned sv = self[(size_t)d * 32 + lane];
    __half2 a01 = e4m3x2_to_h2((unsigned short)(sv & 0xFFFFu));
    __half2 a23 = e4m3x2_to_h2((unsigned short)(sv >> 16));

    int k = start;
    for (; k + 4 <= end; k += 4) {
        int2 e0 = adj[k], e1 = adj[k + 1], e2 = adj[k + 2], e3 = adj[k + 3];
        unsigned v0 = src[(size_t)e0.x * 32 + lane];
        unsigned v1 = src[(size_t)e1.x * 32 + lane];
        unsigned v2 = src[(size_t)e2.x * 32 + lane];
        unsigned v3 = src[(size_t)e3.x * 32 + lane];
        __half2 n0 = *reinterpret_cast<__half2*>(&e0.y);
        __half2 n1 = *reinterpret_cast<__half2*>(&e1.y);
        __half2 n2 = *reinterpret_cast<__half2*>(&e2.y);
        __half2 n3 = *reinterpret_cast<__half2*>(&e3.y);
        a01 = __hfma2(e4m3x2_to_h2((unsigned short)(v0 & 0xFFFFu)), n0, a01);
        a23 = __hfma2(e4m3x2_to_h2((unsigned short)(v0 >> 16)),     n0, a23);
        a01 = __hfma2(e4m3x2_to_h2((unsigned short)(v1 & 0xFFFFu)), n1, a01);
        a23 = __hfma2(e4m3x2_to_h2((unsigned short)(v1 >> 16)),     n1, a23);
        a01 = __hfma2(e4m3x2_to_h2((unsigned short)(v2 & 0xFFFFu)), n2, a01);
        a23 = __hfma2(e4m3x2_to_h2((unsigned short)(v2 >> 16)),     n2, a23);
        a01 = __hfma2(e4m3x2_to_h2((unsigned short)(v3 & 0xFFFFu)), n3, a01);
        a23 = __hfma2(e4m3x2_to_h2((unsigned short)(v3 >> 16)),     n3, a23);
    }
    for (; k < end; k++) {
        int2 e0 = adj[k];
        unsigned v0 = src[(size_t)e0.x * 32 + lane];
        __half2 n0 = *reinterpret_cast<__half2*>(&e0.y);
        a01 = __hfma2(e4m3x2_to_h2((unsigned short)(v0 & 0xFFFFu)), n0, a01);
        a23 = __hfma2(e4m3x2_to_h2((unsigned short)(v0 >> 16)),     n0, a23);
    }

    dst[(size_t)d * 32 + lane] = pack_f8x4(a01, a23);
}

// ---------------- scoring path ----------------

__global__ void acc_init_kernel(const float4* __restrict__ user_feat,
                                const float4* __restrict__ item_feat,
                                const int* __restrict__ ui,
                                const int* __restrict__ ii,
                                float* __restrict__ loss_out,
                                int has_loss) {
    int t = blockIdx.x * blockDim.x + threadIdx.x;
    const int per_row = D_N / 4;
    if (t >= B_N * per_row) return;
    int b = t / per_row;
    int d = t - b * per_row;
    ((float4*)g_acc_u)[t] = user_feat[(size_t)ui[b] * per_row + d];
    ((float4*)g_acc_i)[t] = item_feat[(size_t)ii[b] * per_row + d];
    if (t == 0 && has_loss) *loss_out = 0.0f;
}

// acc += (coef/S) * dequant(fp8 rows just produced)
__global__ void acc_gather_kernel(const unsigned* __restrict__ f8_u,
                                  const unsigned* __restrict__ f8_i,
                                  const int* __restrict__ ui,
                                  const int* __restrict__ ii,
                                  float coef) {
    int t = blockIdx.x * blockDim.x + threadIdx.x;
    const int per_row = D_N / 4;
    if (t >= B_N * per_row) return;
    int b = t / per_row;
    int d = t - b * per_row;
    float c = coef * FP8_INV;

    unsigned q = f8_u[(size_t)ui[b] * per_row + d];
    float2 p = __half22float2(e4m3x2_to_h2((unsigned short)(q & 0xFFFFu)));
    float2 r = __half22float2(e4m3x2_to_h2((unsigned short)(q >> 16)));
    float4 a = ((float4*)g_acc_u)[t];
    a.x += c * p.x; a.y += c * p.y; a.z += c * r.x; a.w += c * r.y;
    ((float4*)g_acc_u)[t] = a;

    unsigned q2 = f8_i[(size_t)ii[b] * per_row + d];
    p = __half22float2(e4m3x2_to_h2((unsigned short)(q2 & 0xFFFFu)));
    r = __half22float2(e4m3x2_to_h2((unsigned short)(q2 >> 16)));
    float4 ai = ((float4*)g_acc_i)[t];
    ai.x += c * p.x; ai.y += c * p.y; ai.z += c * r.x; ai.w += c * r.y;
    ((float4*)g_acc_i)[t] = ai;
}

__global__ void score_kernel(const float* __restrict__ labels,
                             float* __restrict__ pred_out,
                             float* __restrict__ loss_out,
                             int has_loss) {
    int warp = (blockIdx.x * blockDim.x + threadIdx.x) >> 5;
    int lane = threadIdx.x & 31;
    if (warp >= B_N) return;

    const float4* au = (const float4*)(g_acc_u + (size_t)warp * D_N);
    const float4* ai = (const float4*)(g_acc_i + (size_t)warp * D_N);
    float4 a = au[lane];
    float4 b = ai[lane];
    float s = a.x * b.x + a.y * b.y + a.z * b.z + a.w * b.w;
    #pragma unroll
    for (int off = 16; off > 0; off >>= 1)
        s += __shfl_down_sync(0xFFFFFFFFu, s, off);

    if (lane == 0) {
        float z = 1.0f / (1.0f + expf(-s));
        pred_out[warp] = z;
        if (has_loss) {
            float lbl = labels[warp];
            float term = fmaxf(z, 0.0f) - z * lbl + log1pf(expf(-fabsf(z)));
            atomicAdd(loss_out, term * (1.0f / (float)B_N));
        }
    }
}

// ---------------- host launch ----------------
extern "C" void kernel_launch(void* const* d_in, const int* in_sizes, int n_in,
                              void* d_out, int out_size) {
    const float* user_feat = (const float*)d_in[0];
    const float* item_feat = (const float*)d_in[1];
    const int*   u_idx     = (const int*)d_in[2];
    const int*   i_idx     = (const int*)d_in[3];
    const int*   ui        = (const int*)d_in[4];
    const int*   ii        = (const int*)d_in[5];
    const float* labels    = (const float*)d_in[6];

    float* out = (float*)d_out;
    int has_loss = (out_size > B_N) ? 1 : 0;
    float* pred_out = out + (out_size - B_N);
    float* loss_out = out;

    unsigned* hu_base; unsigned* hi_base;
    cudaGetSymbolAddress((void**)&hu_base, g_f8_u);
    cudaGetSymbolAddress((void**)&hi_base, g_f8_i);
    unsigned* hu[2] = { hu_base, hu_base + (size_t)U_N * (D_N / 4) };
    unsigned* hi[2] = { hi_base, hi_base + (size_t)I_N * (D_N / 4) };

    const int T = 256;
    const int acc_blocks = (B_N * (D_N / 4) + T - 1) / T;
    const int conv_blocks = ((U_N + I_N) * (D_N / 4) + T - 1) / T;
    const int row_warp_blocks = ((U_N + I_N) * 32 + T - 1) / T;

    // 1) CSR build
    zero_deg_kernel<<<(U_N + T - 1) / T, T>>>();
    degree_kernel<<<(E_N + T - 1) / T, T>>>(u_idx, i_idx);
    scan_partial_kernel<<<NCH_U + NCH_I, 256>>>();
    scan_chunkoff_kernel<<<1, 128>>>();
    scan_final_kernel<<<NCH_U + NCH_I, 256>>>();
    fill_kernel<<<(E_N + T - 1) / T, T>>>(u_idx, i_idx);

    // 2) fp8 source buffers + scoring accumulators (layer-0 term, exact fp32)
    convert_kernel<<<conv_blocks, T>>>((const float4*)user_feat,
                                       (const float4*)item_feat);
    acc_init_kernel<<<acc_blocks, T>>>((const float4*)user_feat,
                                       (const float4*)item_feat,
                                       ui, ii, loss_out, has_loss);

    // 3) three propagation layers (ping-pong fp8 buffers)
    const float coefs[3] = { 1.0f / 2.0f, 1.0f / 3.0f, 1.0f / 4.0f };
    int cur = 0;
    for (int l = 0; l < 3; l++) {
        int nxt = 1 - cur;
        gather_kernel<<<row_warp_blocks, T>>>(hu[cur], hi[cur],
                                              hu[nxt], hi[nxt]);
        acc_gather_kernel<<<acc_blocks, T>>>(hu[nxt], hi[nxt],
                                             ui, ii, coefs[l]);
        cur = nxt;
    }

    // 4) scoring + loss
    score_kernel<<<(B_N * 32 + T - 1) / T, T>>>(labels, pred_out, loss_out, has_loss);
}